// round 5
// baseline (speedup 1.0000x reference)
#include <cuda_runtime.h>
#include <cuda_bf16.h>
#include <stdint.h>
#include <math.h>

// Problem constants
#define Bz  2
#define Sq  2048
#define Dm  1024
#define Hn  16
#define DHd 64
#define BH  (Bz * Hn)
#define CLOG2E 1.4426950408889634f

// ---------------------------------------------------------------------------
// Scratch (allocation-free __device__ globals)
// ---------------------------------------------------------------------------
__device__ __align__(256) float g_q[(size_t)BH * Sq * DHd];
__device__ __align__(256) float g_k[(size_t)BH * Sq * DHd];
__device__ __align__(256) float g_v[(size_t)BH * Sq * DHd];
__device__ __align__(256) float g_ctx[(size_t)Bz * Sq * Dm];
__device__ __align__(256) float2 g_part[(size_t)BH * Sq * 16];
__device__ __align__(256) float g_croff[(size_t)BH * Sq];
__device__ int g_mask_is_int;

// ---------------------------------------------------------------------------
// Helpers
// ---------------------------------------------------------------------------
__device__ __forceinline__ uint32_t smem_u32(const void* p) {
    return (uint32_t)__cvta_generic_to_shared(p);
}
__device__ __forceinline__ void ldm4(uint32_t* r, uint32_t a) {
    asm volatile("ldmatrix.sync.aligned.m8n8.x4.shared.b16 {%0,%1,%2,%3},[%4];"
                 : "=r"(r[0]), "=r"(r[1]), "=r"(r[2]), "=r"(r[3]) : "r"(a));
}
__device__ __forceinline__ void ldm4t(uint32_t* r, uint32_t a) {
    asm volatile("ldmatrix.sync.aligned.m8n8.x4.trans.shared.b16 {%0,%1,%2,%3},[%4];"
                 : "=r"(r[0]), "=r"(r[1]), "=r"(r[2]), "=r"(r[3]) : "r"(a));
}
__device__ __forceinline__ void mma_bf16(float* c, const uint32_t* a, const uint32_t* b) {
    asm volatile(
        "mma.sync.aligned.m16n8k16.row.col.f32.bf16.bf16.f32 "
        "{%0,%1,%2,%3},{%4,%5,%6,%7},{%8,%9},{%0,%1,%2,%3};"
        : "+f"(c[0]), "+f"(c[1]), "+f"(c[2]), "+f"(c[3])
        : "r"(a[0]), "r"(a[1]), "r"(a[2]), "r"(a[3]), "r"(b[0]), "r"(b[1]));
}
__device__ __forceinline__ void split1(float x, __nv_bfloat16& h, __nv_bfloat16& l) {
    h = __float2bfloat16(x);
    l = __float2bfloat16(x - __bfloat162float(h));
}
__device__ __forceinline__ void split_store(float4 v, __nv_bfloat16* dh,
                                            __nv_bfloat16* dl) {
    __nv_bfloat16 h0, h1, h2, h3, l0, l1, l2, l3;
    split1(v.x, h0, l0); split1(v.y, h1, l1);
    split1(v.z, h2, l2); split1(v.w, h3, l3);
    *(__nv_bfloat162*)(dh)     = __nv_bfloat162{h0, h1};
    *(__nv_bfloat162*)(dh + 2) = __nv_bfloat162{h2, h3};
    *(__nv_bfloat162*)(dl)     = __nv_bfloat162{l0, l1};
    *(__nv_bfloat162*)(dl + 2) = __nv_bfloat162{l2, l3};
}
__device__ __forceinline__ float ex2(float x) {
    float y; asm("ex2.approx.f32 %0,%1;" : "=f"(y) : "f"(x)); return y;
}
__device__ __forceinline__ float lg2(float x) {
    float y; asm("lg2.approx.f32 %0,%1;" : "=f"(y) : "f"(x)); return y;
}
__device__ __forceinline__ void merge_ms(float& m, float& s, float om, float os) {
    float nm = fmaxf(m, om);
    if (nm > -INFINITY) {
        float sa = (m  > -INFINITY) ? s  * ex2((m  - nm) * CLOG2E) : 0.f;
        float sb = (om > -INFINITY) ? os * ex2((om - nm) * CLOG2E) : 0.f;
        s = sa + sb;
    }
    m = nm;
}

// ---------------------------------------------------------------------------
// Mask dtype detector
// ---------------------------------------------------------------------------
__global__ void detect_mask_kernel(const unsigned char* __restrict__ m) {
    __shared__ int any;
    if (threadIdx.x == 0) any = 0;
    __syncthreads();
    int local = 0;
    for (int i = threadIdx.x; i < Bz * Sq; i += blockDim.x)
        if ((i & 3) && m[i]) local = 1;
    if (local) atomicOr(&any, 1);
    __syncthreads();
    if (threadIdx.x == 0) g_mask_is_int = (any == 0) ? 1 : 0;
}

// ---------------------------------------------------------------------------
// Projection GEMM: fp32 in, inline hi/lo split, 128x128x64 tiles, 8 warps.
// MODE 0: head-split f32 epilogue -> [BH,S,DH]; MODE 1: plain f32 epilogue.
// ---------------------------------------------------------------------------
template <int MODE>
__global__ void __launch_bounds__(256) proj_gemm(
    const float* __restrict__ A, const float* __restrict__ W,
    const float* __restrict__ bias, float* __restrict__ C)
{
    constexpr int SA = 72, SB = 136;
    extern __shared__ __nv_bfloat16 sm[];
    __nv_bfloat16* Ah = sm;
    __nv_bfloat16* Al = Ah + 128 * SA;
    __nv_bfloat16* Bh = Al + 128 * SA;
    __nv_bfloat16* Bl = Bh + 64 * SB;

    const int tid = threadIdx.x, lane = tid & 31, warp = tid >> 5;
    const int wm = (warp >> 2) * 64;
    const int wn = (warp & 3) * 32;
    const int bm = blockIdx.y * 128;
    const int bn = blockIdx.x * 128;

    float acc[4][4][4];
#pragma unroll
    for (int i = 0; i < 4; i++)
#pragma unroll
        for (int j = 0; j < 4; j++)
#pragma unroll
            for (int q = 0; q < 4; q++) acc[i][j][q] = 0.f;

    const uint32_t aH = smem_u32(Ah), aL = smem_u32(Al);
    const uint32_t bH = smem_u32(Bh), bL = smem_u32(Bl);

    for (int k0 = 0; k0 < Dm; k0 += 64) {
#pragma unroll
        for (int r = 0; r < 8; r++) {
            const int idx = tid + r * 256;
            const int m = idx >> 4, kq = (idx & 15) * 4;
            float4 v = *(const float4*)(A + (size_t)(bm + m) * Dm + k0 + kq);
            split_store(v, &Ah[m * SA + kq], &Al[m * SA + kq]);
        }
#pragma unroll
        for (int r = 0; r < 8; r++) {
            const int idx = tid + r * 256;
            const int kr = idx >> 5, n4 = (idx & 31) * 4;
            float4 v = *(const float4*)(W + (size_t)(k0 + kr) * Dm + bn + n4);
            split_store(v, &Bh[kr * SB + n4], &Bl[kr * SB + n4]);
        }
        __syncthreads();

#pragma unroll
        for (int kk = 0; kk < 64; kk += 16) {
            uint32_t ah[4][4], al[4][4];
            const int arow = wm + (lane & 7) + ((lane >> 3) & 1) * 8;
            const int acol = kk + (lane >> 4) * 8;
#pragma unroll
            for (int mt = 0; mt < 4; mt++) {
                const uint32_t off = (uint32_t)(((arow + mt * 16) * SA + acol) * 2);
                ldm4(ah[mt], aH + off);
                ldm4(al[mt], aL + off);
            }
            uint32_t bh[4][2], bl[4][2];
            const int brow = kk + (lane & 7) + ((lane >> 3) & 1) * 8;
#pragma unroll
            for (int sp = 0; sp < 2; sp++) {
                const int bcol = wn + sp * 16 + (lane >> 4) * 8;
                const uint32_t off = (uint32_t)((brow * SB + bcol) * 2);
                uint32_t t[4];
                ldm4t(t, bH + off);
                bh[2 * sp][0] = t[0]; bh[2 * sp][1] = t[1];
                bh[2 * sp + 1][0] = t[2]; bh[2 * sp + 1][1] = t[3];
                ldm4t(t, bL + off);
                bl[2 * sp][0] = t[0]; bl[2 * sp][1] = t[1];
                bl[2 * sp + 1][0] = t[2]; bl[2 * sp + 1][1] = t[3];
            }
#pragma unroll
            for (int mt = 0; mt < 4; mt++)
#pragma unroll
                for (int nt = 0; nt < 4; nt++) {
                    mma_bf16(acc[mt][nt], ah[mt], bh[nt]);
                    mma_bf16(acc[mt][nt], ah[mt], bl[nt]);
                    mma_bf16(acc[mt][nt], al[mt], bh[nt]);
                }
        }
        __syncthreads();
    }

    const int g = lane >> 2, t2 = (lane & 3) * 2;
#pragma unroll
    for (int mt = 0; mt < 4; mt++)
#pragma unroll
        for (int nt = 0; nt < 4; nt++) {
            const int col = bn + wn + nt * 8 + t2;
#pragma unroll
            for (int h2 = 0; h2 < 2; h2++) {
                const int row = bm + wm + mt * 16 + g + h2 * 8;
                float c0 = acc[mt][nt][h2 * 2 + 0] + bias[col];
                float c1 = acc[mt][nt][h2 * 2 + 1] + bias[col + 1];
                if (MODE == 0) {
                    const int bb = row >> 11, ss = row & (Sq - 1);
                    const int hh = col >> 6,  dh = col & (DHd - 1);
                    *(float2*)(C + (((size_t)(bb * Hn + hh)) * Sq + ss) * DHd + dh)
                        = make_float2(c0, c1);
                } else {
                    *(float2*)(C + (size_t)row * Dm + col) = make_float2(c0, c1);
                }
            }
        }
}

// ---------------------------------------------------------------------------
// Scores: 128x128 tile per block, K=64 single-shot. Raw masked/scaled scores
// to attn + per-(row, col-tile) partial (max, expsum) stats to g_part.
// ---------------------------------------------------------------------------
__global__ void __launch_bounds__(256) scores_kernel(
    const void* __restrict__ mask, float* __restrict__ attn)
{
    constexpr int SA = 72;
    extern __shared__ char smraw[];
    __nv_bfloat16* Qh = (__nv_bfloat16*)smraw;
    __nv_bfloat16* Ql = Qh + 128 * SA;
    __nv_bfloat16* Kh = Ql + 128 * SA;
    __nv_bfloat16* Kl = Kh + 128 * SA;
    float* smM = (float*)(Kl + 128 * SA);   // [128][4]
    float* smS = smM + 512;

    const int z = blockIdx.z, zb = z / Hn;
    const int bm = blockIdx.y * 128;
    const int bn = blockIdx.x * 128;
    const float* q = g_q + (size_t)z * Sq * DHd;
    const float* k = g_k + (size_t)z * Sq * DHd;

    const int tid = threadIdx.x, lane = tid & 31, warp = tid >> 5;
    const int wm = (warp >> 2) * 64;
    const int wn = (warp & 3) * 32;

#pragma unroll
    for (int r = 0; r < 8; r++) {
        const int idx = tid + r * 256;
        const int m = idx >> 4, kq = (idx & 15) * 4;
        float4 a = *(const float4*)(q + (size_t)(bm + m) * DHd + kq);
        split_store(a, &Qh[m * SA + kq], &Ql[m * SA + kq]);
        float4 b = *(const float4*)(k + (size_t)(bn + m) * DHd + kq);
        split_store(b, &Kh[m * SA + kq], &Kl[m * SA + kq]);
    }
    __syncthreads();

    float acc[4][4][4];
#pragma unroll
    for (int i = 0; i < 4; i++)
#pragma unroll
        for (int j = 0; j < 4; j++)
#pragma unroll
            for (int q2 = 0; q2 < 4; q2++) acc[i][j][q2] = 0.f;

    const uint32_t aH = smem_u32(Qh), aL = smem_u32(Ql);
    const uint32_t bH = smem_u32(Kh), bL = smem_u32(Kl);

#pragma unroll
    for (int kk = 0; kk < DHd; kk += 16) {
        uint32_t ah[4][4], al[4][4];
        const int arow = wm + (lane & 7) + ((lane >> 3) & 1) * 8;
        const int acol = kk + (lane >> 4) * 8;
#pragma unroll
        for (int mt = 0; mt < 4; mt++) {
            const uint32_t off = (uint32_t)(((arow + mt * 16) * SA + acol) * 2);
            ldm4(ah[mt], aH + off);
            ldm4(al[mt], aL + off);
        }
        uint32_t bh[4][2], bl[4][2];
#pragma unroll
        for (int sp = 0; sp < 2; sp++) {
            const int brow = wn + sp * 16 + (lane & 7) + ((lane >> 3) & 1) * 8;
            const int bcol = kk + (lane >> 4) * 8;
            const uint32_t off = (uint32_t)((brow * SA + bcol) * 2);
            uint32_t t[4];
            ldm4(t, bH + off);
            bh[2 * sp][0] = t[0]; bh[2 * sp + 1][0] = t[1];
            bh[2 * sp][1] = t[2]; bh[2 * sp + 1][1] = t[3];
            ldm4(t, bL + off);
            bl[2 * sp][0] = t[0]; bl[2 * sp + 1][0] = t[1];
            bl[2 * sp][1] = t[2]; bl[2 * sp + 1][1] = t[3];
        }
#pragma unroll
        for (int mt = 0; mt < 4; mt++)
#pragma unroll
            for (int nt = 0; nt < 4; nt++) {
                mma_bf16(acc[mt][nt], ah[mt], bh[nt]);
                mma_bf16(acc[mt][nt], ah[mt], bl[nt]);
                mma_bf16(acc[mt][nt], al[mt], bh[nt]);
            }
    }

    // epilogue: mask+scale, write raw scores, per-row partial stats
    const int g = lane >> 2, t2 = (lane & 3) * 2;
    const int mint = g_mask_is_int;
    const float NEG_INF = __int_as_float(0xff800000);
    bool mb[8];
#pragma unroll
    for (int nt = 0; nt < 4; nt++) {
        const int col = bn + wn + nt * 8 + t2;
        if (mint) {
            mb[2 * nt]     = ((const int*)mask)[zb * Sq + col] != 0;
            mb[2 * nt + 1] = ((const int*)mask)[zb * Sq + col + 1] != 0;
        } else {
            mb[2 * nt]     = ((const unsigned char*)mask)[zb * Sq + col] != 0;
            mb[2 * nt + 1] = ((const unsigned char*)mask)[zb * Sq + col + 1] != 0;
        }
    }
    float stm[8], sts[8];
#pragma unroll
    for (int mt = 0; mt < 4; mt++)
#pragma unroll
        for (int h2 = 0; h2 < 2; h2++) {
            const int row = bm + wm + mt * 16 + g + h2 * 8;
            float* rp = attn + ((size_t)z * Sq + row) * Sq;
            float v8[8], tm = -INFINITY;
#pragma unroll
            for (int nt = 0; nt < 4; nt++) {
                float v0 = mb[2 * nt]     ? acc[mt][nt][h2 * 2 + 0] * 0.125f : NEG_INF;
                float v1 = mb[2 * nt + 1] ? acc[mt][nt][h2 * 2 + 1] * 0.125f : NEG_INF;
                *(float2*)(rp + bn + wn + nt * 8 + t2) = make_float2(v0, v1);
                v8[2 * nt] = v0; v8[2 * nt + 1] = v1;
                tm = fmaxf(tm, fmaxf(v0, v1));
            }
            float ts = 0.f;
            if (tm > -INFINITY) {
#pragma unroll
                for (int i = 0; i < 8; i++)
                    ts += ex2((v8[i] - tm) * CLOG2E);
            }
            stm[mt * 2 + h2] = tm; sts[mt * 2 + h2] = ts;
        }
#pragma unroll
    for (int o = 1; o <= 2; o <<= 1)
#pragma unroll
        for (int s = 0; s < 8; s++) {
            float om = __shfl_xor_sync(~0u, stm[s], o);
            float os = __shfl_xor_sync(~0u, sts[s], o);
            merge_ms(stm[s], sts[s], om, os);
        }
    if ((lane & 3) == 0) {
#pragma unroll
        for (int mt = 0; mt < 4; mt++)
#pragma unroll
            for (int h2 = 0; h2 < 2; h2++) {
                const int rl = wm + mt * 16 + g + h2 * 8;
                smM[rl * 4 + (warp & 3)] = stm[mt * 2 + h2];
                smS[rl * 4 + (warp & 3)] = sts[mt * 2 + h2];
            }
    }
    __syncthreads();
    if (tid < 128) {
        float m = -INFINITY, s = 0.f;
#pragma unroll
        for (int j = 0; j < 4; j++)
            merge_ms(m, s, smM[tid * 4 + j], smS[tid * 4 + j]);
        g_part[((size_t)z * Sq + bm + tid) * 16 + blockIdx.x] = make_float2(m, s);
    }
}

// ---------------------------------------------------------------------------
// Merge per-tile stats -> croff[row] = m*log2e + log2(sum)
// ---------------------------------------------------------------------------
__global__ void stats_merge_kernel() {
    const int r = blockIdx.x * blockDim.x + threadIdx.x;
    const float2* p = g_part + (size_t)r * 16;
    float m = -INFINITY, s = 0.f;
#pragma unroll
    for (int j = 0; j < 16; j++) {
        float2 v = p[j];
        merge_ms(m, s, v.x, v.y);
    }
    g_croff[r] = fmaf(m, CLOG2E, lg2(s));
}

// ---------------------------------------------------------------------------
// Ctx: reads raw scores, normalizes inline (p = ex2(s*log2e - croff)),
// writes normalized attn in place, MMAs p (split) with V (split) -> f32 ctx.
// ---------------------------------------------------------------------------
__global__ void __launch_bounds__(256) ctx_kernel(float* __restrict__ attn)
{
    constexpr int SA = 72, SB = 72;
    extern __shared__ char smraw[];
    __nv_bfloat16* Ph = (__nv_bfloat16*)smraw;
    __nv_bfloat16* Pl = Ph + 128 * SA;
    __nv_bfloat16* Vh = Pl + 128 * SA;
    __nv_bfloat16* Vl = Vh + 64 * SB;
    float* crf = (float*)(Vl + 64 * SB);    // [128]

    const int z = blockIdx.z, zb = z / Hn, zh = z % Hn;
    const int bm = blockIdx.y * 128;
    float* P = attn + (size_t)z * Sq * Sq;
    const float* V = g_v + (size_t)z * Sq * DHd;

    const int tid = threadIdx.x, lane = tid & 31, warp = tid >> 5;
    const int wm = (warp >> 2) * 64;
    const int wn = (warp & 3) * 16;

    if (tid < 128) crf[tid] = g_croff[(size_t)z * Sq + bm + tid];
    __syncthreads();

    float acc[4][2][4];
#pragma unroll
    for (int i = 0; i < 4; i++)
#pragma unroll
        for (int j = 0; j < 2; j++)
#pragma unroll
            for (int q = 0; q < 4; q++) acc[i][j][q] = 0.f;

    const uint32_t aH = smem_u32(Ph), aL = smem_u32(Pl);
    const uint32_t bH = smem_u32(Vh), bL = smem_u32(Vl);

    for (int k0 = 0; k0 < Sq; k0 += 64) {
        // P fill: read raw, normalize, write back, split into smem
#pragma unroll
        for (int r = 0; r < 8; r++) {
            const int idx = tid + r * 256;
            const int m = idx >> 4, kq = (idx & 15) * 4;
            float* rp = P + (size_t)(bm + m) * Sq + k0 + kq;
            const float cr = crf[m];
            float4 v = *(float4*)rp;
            v.x = ex2(fmaf(v.x, CLOG2E, -cr));
            v.y = ex2(fmaf(v.y, CLOG2E, -cr));
            v.z = ex2(fmaf(v.z, CLOG2E, -cr));
            v.w = ex2(fmaf(v.w, CLOG2E, -cr));
            *(float4*)rp = v;
            split_store(v, &Ph[m * SA + kq], &Pl[m * SA + kq]);
        }
        // V fill: 64 x 64
#pragma unroll
        for (int r = 0; r < 4; r++) {
            const int idx = tid + r * 256;
            const int kr = idx >> 4, n4 = (idx & 15) * 4;
            float4 v = *(const float4*)(V + (size_t)(k0 + kr) * DHd + n4);
            split_store(v, &Vh[kr * SB + n4], &Vl[kr * SB + n4]);
        }
        __syncthreads();

#pragma unroll
        for (int kk = 0; kk < 64; kk += 16) {
            uint32_t ah[4][4], al[4][4];
            const int arow = wm + (lane & 7) + ((lane >> 3) & 1) * 8;
            const int acol = kk + (lane >> 4) * 8;
#pragma unroll
            for (int mt = 0; mt < 4; mt++) {
                const uint32_t off = (uint32_t)(((arow + mt * 16) * SA + acol) * 2);
                ldm4(ah[mt], aH + off);
                ldm4(al[mt], aL + off);
            }
            uint32_t bh[2][2], bl[2][2];
            {
                const int brow = kk + (lane & 7) + ((lane >> 3) & 1) * 8;
                const int bcol = wn + (lane >> 4) * 8;
                const uint32_t off = (uint32_t)((brow * SB + bcol) * 2);
                uint32_t t[4];
                ldm4t(t, bH + off);
                bh[0][0] = t[0]; bh[0][1] = t[1];
                bh[1][0] = t[2]; bh[1][1] = t[3];
                ldm4t(t, bL + off);
                bl[0][0] = t[0]; bl[0][1] = t[1];
                bl[1][0] = t[2]; bl[1][1] = t[3];
            }
#pragma unroll
            for (int mt = 0; mt < 4; mt++)
#pragma unroll
                for (int nt = 0; nt < 2; nt++) {
                    mma_bf16(acc[mt][nt], ah[mt], bh[nt]);
                    mma_bf16(acc[mt][nt], ah[mt], bl[nt]);
                    mma_bf16(acc[mt][nt], al[mt], bh[nt]);
                }
        }
        __syncthreads();
    }

    const int g = lane >> 2, t2 = (lane & 3) * 2;
#pragma unroll
    for (int mt = 0; mt < 4; mt++)
#pragma unroll
        for (int nt = 0; nt < 2; nt++) {
            const int col = wn + nt * 8 + t2;
#pragma unroll
            for (int h2 = 0; h2 < 2; h2++) {
                const int row = bm + wm + mt * 16 + g + h2 * 8;
                *(float2*)(g_ctx + ((size_t)zb * Sq + row) * Dm + zh * DHd + col)
                    = make_float2(acc[mt][nt][h2 * 2 + 0], acc[mt][nt][h2 * 2 + 1]);
            }
        }
}

// ---------------------------------------------------------------------------
// Launch. Inputs: qs ks vs mask Wq bq Wk bk Wv bv Wo bo.
// d_out: out [B,S,D] then attn [B,H,S,S].
// ---------------------------------------------------------------------------
extern "C" void kernel_launch(void* const* d_in, const int* in_sizes, int n_in,
                              void* d_out, int out_size)
{
    const float* qs = (const float*)d_in[0];
    const float* ks = (const float*)d_in[1];
    const float* vs = (const float*)d_in[2];
    const void*  mask = d_in[3];
    const float* Wq = (const float*)d_in[4];
    const float* bq = (const float*)d_in[5];
    const float* Wk = (const float*)d_in[6];
    const float* bk = (const float*)d_in[7];
    const float* Wv = (const float*)d_in[8];
    const float* bv = (const float*)d_in[9];
    const float* Wo = (const float*)d_in[10];
    const float* bo = (const float*)d_in[11];

    float* out  = (float*)d_out;
    float* attn = out + (size_t)Bz * Sq * Dm;

    const int SM_PROJ   = (2 * 128 * 72 + 2 * 64 * 136) * 2;          // 71680
    const int SM_SCORES = 4 * 128 * 72 * 2 + 2 * 512 * 4;             // 77824
    const int SM_CTX    = (2 * 128 * 72 + 2 * 64 * 72) * 2 + 512;     // 55808

    cudaFuncSetAttribute(proj_gemm<0>, cudaFuncAttributeMaxDynamicSharedMemorySize, SM_PROJ);
    cudaFuncSetAttribute(proj_gemm<1>, cudaFuncAttributeMaxDynamicSharedMemorySize, SM_PROJ);
    cudaFuncSetAttribute(scores_kernel, cudaFuncAttributeMaxDynamicSharedMemorySize, SM_SCORES);
    cudaFuncSetAttribute(ctx_kernel, cudaFuncAttributeMaxDynamicSharedMemorySize, SM_CTX);

    float *gq, *gk, *gv, *gctx;
    cudaGetSymbolAddress((void**)&gq, g_q);
    cudaGetSymbolAddress((void**)&gk, g_k);
    cudaGetSymbolAddress((void**)&gv, g_v);
    cudaGetSymbolAddress((void**)&gctx, g_ctx);

    detect_mask_kernel<<<1, 256>>>((const unsigned char*)mask);

    dim3 gProj(Dm / 128, (Bz * Sq) / 128);  // (8, 32)
    proj_gemm<0><<<gProj, 256, SM_PROJ>>>(qs, Wq, bq, gq);
    proj_gemm<0><<<gProj, 256, SM_PROJ>>>(ks, Wk, bk, gk);
    proj_gemm<0><<<gProj, 256, SM_PROJ>>>(vs, Wv, bv, gv);

    scores_kernel<<<dim3(Sq / 128, Sq / 128, BH), 256, SM_SCORES>>>(mask, attn);

    stats_merge_kernel<<<(BH * Sq) / 256, 256>>>();

    ctx_kernel<<<dim3(1, Sq / 128, BH), 256, SM_CTX>>>(attn);

    proj_gemm<1><<<gProj, 256, SM_PROJ>>>(gctx, Wo, bo, out);
}

// round 6
// speedup vs baseline: 1.3010x; 1.3010x over previous
#include <cuda_runtime.h>
#include <cuda_bf16.h>
#include <stdint.h>
#include <math.h>

// Problem constants
#define Bz  2
#define Sq  2048
#define Dm  1024
#define Hn  16
#define DHd 64
#define BH  (Bz * Hn)
#define CLOG2E 1.4426950408889634f

// ---------------------------------------------------------------------------
// Scratch (allocation-free __device__ globals)
// ---------------------------------------------------------------------------
__device__ __align__(256) float g_q[(size_t)BH * Sq * DHd];
__device__ __align__(256) float g_k[(size_t)BH * Sq * DHd];
__device__ __align__(256) float g_v[(size_t)BH * Sq * DHd];
__device__ __align__(256) float g_ctx[(size_t)Bz * Sq * Dm];
__device__ __align__(256) float2 g_part[(size_t)BH * Sq * 16];
__device__ __align__(256) float g_croff[(size_t)BH * Sq];
__device__ int g_mask_is_int;

// ---------------------------------------------------------------------------
// Helpers
// ---------------------------------------------------------------------------
__device__ __forceinline__ uint32_t smem_u32(const void* p) {
    return (uint32_t)__cvta_generic_to_shared(p);
}
__device__ __forceinline__ void ldm4(uint32_t* r, uint32_t a) {
    asm volatile("ldmatrix.sync.aligned.m8n8.x4.shared.b16 {%0,%1,%2,%3},[%4];"
                 : "=r"(r[0]), "=r"(r[1]), "=r"(r[2]), "=r"(r[3]) : "r"(a));
}
__device__ __forceinline__ void ldm4t(uint32_t* r, uint32_t a) {
    asm volatile("ldmatrix.sync.aligned.m8n8.x4.trans.shared.b16 {%0,%1,%2,%3},[%4];"
                 : "=r"(r[0]), "=r"(r[1]), "=r"(r[2]), "=r"(r[3]) : "r"(a));
}
__device__ __forceinline__ void mma_bf16(float* c, const uint32_t* a, const uint32_t* b) {
    asm volatile(
        "mma.sync.aligned.m16n8k16.row.col.f32.bf16.bf16.f32 "
        "{%0,%1,%2,%3},{%4,%5,%6,%7},{%8,%9},{%0,%1,%2,%3};"
        : "+f"(c[0]), "+f"(c[1]), "+f"(c[2]), "+f"(c[3])
        : "r"(a[0]), "r"(a[1]), "r"(a[2]), "r"(a[3]), "r"(b[0]), "r"(b[1]));
}
__device__ __forceinline__ void split1(float x, __nv_bfloat16& h, __nv_bfloat16& l) {
    h = __float2bfloat16(x);
    l = __float2bfloat16(x - __bfloat162float(h));
}
__device__ __forceinline__ float ex2(float x) {
    float y; asm("ex2.approx.f32 %0,%1;" : "=f"(y) : "f"(x)); return y;
}
__device__ __forceinline__ float lg2(float x) {
    float y; asm("lg2.approx.f32 %0,%1;" : "=f"(y) : "f"(x)); return y;
}
__device__ __forceinline__ void merge_ms(float& m, float& s, float om, float os) {
    float nm = fmaxf(m, om);
    if (nm > -INFINITY) {
        float sa = (m  > -INFINITY) ? s  * ex2((m  - nm) * CLOG2E) : 0.f;
        float sb = (om > -INFINITY) ? os * ex2((om - nm) * CLOG2E) : 0.f;
        s = sa + sb;
    }
    m = nm;
}

// ---------------------------------------------------------------------------
// Mask dtype detector
// ---------------------------------------------------------------------------
__global__ void detect_mask_kernel(const unsigned char* __restrict__ m) {
    __shared__ int any;
    if (threadIdx.x == 0) any = 0;
    __syncthreads();
    int local = 0;
    for (int i = threadIdx.x; i < Bz * Sq; i += blockDim.x)
        if ((i & 3) && m[i]) local = 1;
    if (local) atomicOr(&any, 1);
    __syncthreads();
    if (threadIdx.x == 0) g_mask_is_int = (any == 0) ? 1 : 0;
}

// ---------------------------------------------------------------------------
// Projection GEMM — EXACT R2 config: 128x128x32, static smem, inline split.
// MODE 0: head-split f32 epilogue -> [BH,S,DH]; MODE 1: plain f32 epilogue.
// ---------------------------------------------------------------------------
template <int MODE>
__global__ void __launch_bounds__(256) proj_gemm(
    const float* __restrict__ A, const float* __restrict__ W,
    const float* __restrict__ bias, float* __restrict__ C)
{
    constexpr int SA = 40, SB = 136;
    __shared__ __nv_bfloat16 Ah[128 * SA], Al[128 * SA];
    __shared__ __nv_bfloat16 Bh[32 * SB],  Bl[32 * SB];

    const int tid = threadIdx.x, lane = tid & 31, warp = tid >> 5;
    const int wm = (warp >> 2) * 64;
    const int wn = (warp & 3) * 32;
    const int bm = blockIdx.y * 128;
    const int bn = blockIdx.x * 128;

    float acc[4][4][4];
#pragma unroll
    for (int i = 0; i < 4; i++)
#pragma unroll
        for (int j = 0; j < 4; j++)
#pragma unroll
            for (int q = 0; q < 4; q++) acc[i][j][q] = 0.f;

    const uint32_t aH = smem_u32(Ah), aL = smem_u32(Al);
    const uint32_t bH = smem_u32(Bh), bL = smem_u32(Bl);

    for (int k0 = 0; k0 < Dm; k0 += 32) {
#pragma unroll
        for (int r = 0; r < 4; r++) {
            const int m  = (tid >> 3) + r * 32;
            const int kq = (tid & 7) * 4;
            float4 v = *(const float4*)(A + (size_t)(bm + m) * Dm + k0 + kq);
            __nv_bfloat16 h0, h1, h2, h3, l0, l1, l2, l3;
            split1(v.x, h0, l0); split1(v.y, h1, l1);
            split1(v.z, h2, l2); split1(v.w, h3, l3);
            *(__nv_bfloat162*)&Ah[m * SA + kq]     = __nv_bfloat162{h0, h1};
            *(__nv_bfloat162*)&Ah[m * SA + kq + 2] = __nv_bfloat162{h2, h3};
            *(__nv_bfloat162*)&Al[m * SA + kq]     = __nv_bfloat162{l0, l1};
            *(__nv_bfloat162*)&Al[m * SA + kq + 2] = __nv_bfloat162{l2, l3};
        }
#pragma unroll
        for (int r = 0; r < 4; r++) {
            const int kr = (tid >> 5) + r * 8;
            const int n4 = (tid & 31) * 4;
            float4 v = *(const float4*)(W + (size_t)(k0 + kr) * Dm + bn + n4);
            __nv_bfloat16 h0, h1, h2, h3, l0, l1, l2, l3;
            split1(v.x, h0, l0); split1(v.y, h1, l1);
            split1(v.z, h2, l2); split1(v.w, h3, l3);
            *(__nv_bfloat162*)&Bh[kr * SB + n4]     = __nv_bfloat162{h0, h1};
            *(__nv_bfloat162*)&Bh[kr * SB + n4 + 2] = __nv_bfloat162{h2, h3};
            *(__nv_bfloat162*)&Bl[kr * SB + n4]     = __nv_bfloat162{l0, l1};
            *(__nv_bfloat162*)&Bl[kr * SB + n4 + 2] = __nv_bfloat162{l2, l3};
        }
        __syncthreads();

#pragma unroll
        for (int kk = 0; kk < 32; kk += 16) {
            uint32_t ah[4][4], al[4][4];
            const int arow = wm + (lane & 7) + ((lane >> 3) & 1) * 8;
            const int acol = kk + (lane >> 4) * 8;
#pragma unroll
            for (int mt = 0; mt < 4; mt++) {
                const uint32_t off = (uint32_t)(((arow + mt * 16) * SA + acol) * 2);
                ldm4(ah[mt], aH + off);
                ldm4(al[mt], aL + off);
            }
            uint32_t bh[4][2], bl[4][2];
            const int brow = kk + (lane & 7) + ((lane >> 3) & 1) * 8;
#pragma unroll
            for (int sp = 0; sp < 2; sp++) {
                const int bcol = wn + sp * 16 + (lane >> 4) * 8;
                const uint32_t off = (uint32_t)((brow * SB + bcol) * 2);
                uint32_t t[4];
                ldm4t(t, bH + off);
                bh[2 * sp][0] = t[0]; bh[2 * sp][1] = t[1];
                bh[2 * sp + 1][0] = t[2]; bh[2 * sp + 1][1] = t[3];
                ldm4t(t, bL + off);
                bl[2 * sp][0] = t[0]; bl[2 * sp][1] = t[1];
                bl[2 * sp + 1][0] = t[2]; bl[2 * sp + 1][1] = t[3];
            }
#pragma unroll
            for (int mt = 0; mt < 4; mt++)
#pragma unroll
                for (int nt = 0; nt < 4; nt++) {
                    mma_bf16(acc[mt][nt], ah[mt], bh[nt]);
                    mma_bf16(acc[mt][nt], ah[mt], bl[nt]);
                    mma_bf16(acc[mt][nt], al[mt], bh[nt]);
                }
        }
        __syncthreads();
    }

    const int g = lane >> 2, t2 = (lane & 3) * 2;
#pragma unroll
    for (int mt = 0; mt < 4; mt++)
#pragma unroll
        for (int nt = 0; nt < 4; nt++) {
            const int col = bn + wn + nt * 8 + t2;
#pragma unroll
            for (int h2 = 0; h2 < 2; h2++) {
                const int row = bm + wm + mt * 16 + g + h2 * 8;
                float c0 = acc[mt][nt][h2 * 2 + 0] + bias[col];
                float c1 = acc[mt][nt][h2 * 2 + 1] + bias[col + 1];
                if (MODE == 0) {
                    const int bb = row >> 11, ss = row & (Sq - 1);
                    const int hh = col >> 6,  dh = col & (DHd - 1);
                    *(float2*)(C + (((size_t)(bb * Hn + hh)) * Sq + ss) * DHd + dh)
                        = make_float2(c0, c1);
                } else {
                    *(float2*)(C + (size_t)row * Dm + col) = make_float2(c0, c1);
                }
            }
        }
}

// ---------------------------------------------------------------------------
// Scores — R2 mainloop (BK=32, static smem, grid 16x16x32) + stats epilogue.
// Writes raw masked/scaled scores; per-(row, col-tile) (max, expsum) -> g_part.
// ---------------------------------------------------------------------------
__global__ void __launch_bounds__(256) scores_kernel(
    const void* __restrict__ mask, float* __restrict__ attn)
{
    constexpr int SA = 40, SB = 40;
    __shared__ __nv_bfloat16 Ah[128 * SA], Al[128 * SA];
    __shared__ __nv_bfloat16 Bh[128 * SB], Bl[128 * SB];
    __shared__ float smM[512], smS[512];

    const int z = blockIdx.z, zb = z / Hn;
    const float* q = g_q + (size_t)z * Sq * DHd;
    const float* k = g_k + (size_t)z * Sq * DHd;

    const int tid = threadIdx.x, lane = tid & 31, warp = tid >> 5;
    const int wm = (warp >> 2) * 64;
    const int wn = (warp & 3) * 32;
    const int bm = blockIdx.y * 128;
    const int bn = blockIdx.x * 128;

    float acc[4][4][4];
#pragma unroll
    for (int i = 0; i < 4; i++)
#pragma unroll
        for (int j = 0; j < 4; j++)
#pragma unroll
            for (int q2 = 0; q2 < 4; q2++) acc[i][j][q2] = 0.f;

    const uint32_t aH = smem_u32(Ah), aL = smem_u32(Al);
    const uint32_t bH = smem_u32(Bh), bL = smem_u32(Bl);

    for (int k0 = 0; k0 < DHd; k0 += 32) {
#pragma unroll
        for (int r = 0; r < 4; r++) {
            const int m  = (tid >> 3) + r * 32;
            const int kq = (tid & 7) * 4;
            float4 a = *(const float4*)(q + (size_t)(bm + m) * DHd + k0 + kq);
            __nv_bfloat16 h0, h1, h2, h3, l0, l1, l2, l3;
            split1(a.x, h0, l0); split1(a.y, h1, l1);
            split1(a.z, h2, l2); split1(a.w, h3, l3);
            *(__nv_bfloat162*)&Ah[m * SA + kq]     = __nv_bfloat162{h0, h1};
            *(__nv_bfloat162*)&Ah[m * SA + kq + 2] = __nv_bfloat162{h2, h3};
            *(__nv_bfloat162*)&Al[m * SA + kq]     = __nv_bfloat162{l0, l1};
            *(__nv_bfloat162*)&Al[m * SA + kq + 2] = __nv_bfloat162{l2, l3};
            float4 b = *(const float4*)(k + (size_t)(bn + m) * DHd + k0 + kq);
            split1(b.x, h0, l0); split1(b.y, h1, l1);
            split1(b.z, h2, l2); split1(b.w, h3, l3);
            *(__nv_bfloat162*)&Bh[m * SB + kq]     = __nv_bfloat162{h0, h1};
            *(__nv_bfloat162*)&Bh[m * SB + kq + 2] = __nv_bfloat162{h2, h3};
            *(__nv_bfloat162*)&Bl[m * SB + kq]     = __nv_bfloat162{l0, l1};
            *(__nv_bfloat162*)&Bl[m * SB + kq + 2] = __nv_bfloat162{l2, l3};
        }
        __syncthreads();

#pragma unroll
        for (int kk = 0; kk < 32; kk += 16) {
            uint32_t ah[4][4], al[4][4];
            const int arow = wm + (lane & 7) + ((lane >> 3) & 1) * 8;
            const int acol = kk + (lane >> 4) * 8;
#pragma unroll
            for (int mt = 0; mt < 4; mt++) {
                const uint32_t off = (uint32_t)(((arow + mt * 16) * SA + acol) * 2);
                ldm4(ah[mt], aH + off);
                ldm4(al[mt], aL + off);
            }
            uint32_t bh[4][2], bl[4][2];
#pragma unroll
            for (int sp = 0; sp < 2; sp++) {
                const int brow = wn + sp * 16 + (lane & 7) + ((lane >> 3) & 1) * 8;
                const int bcol = kk + (lane >> 4) * 8;
                const uint32_t off = (uint32_t)((brow * SB + bcol) * 2);
                uint32_t t[4];
                ldm4(t, bH + off);
                bh[2 * sp][0] = t[0]; bh[2 * sp + 1][0] = t[1];
                bh[2 * sp][1] = t[2]; bh[2 * sp + 1][1] = t[3];
                ldm4(t, bL + off);
                bl[2 * sp][0] = t[0]; bl[2 * sp + 1][0] = t[1];
                bl[2 * sp][1] = t[2]; bl[2 * sp + 1][1] = t[3];
            }
#pragma unroll
            for (int mt = 0; mt < 4; mt++)
#pragma unroll
                for (int nt = 0; nt < 4; nt++) {
                    mma_bf16(acc[mt][nt], ah[mt], bh[nt]);
                    mma_bf16(acc[mt][nt], ah[mt], bl[nt]);
                    mma_bf16(acc[mt][nt], al[mt], bh[nt]);
                }
        }
        __syncthreads();
    }

    // epilogue: mask+scale, write raw scores, partial row stats
    const int g = lane >> 2, t2 = (lane & 3) * 2;
    const int mint = g_mask_is_int;
    const float NEG_INF = __int_as_float(0xff800000);
    bool mb[8];
#pragma unroll
    for (int nt = 0; nt < 4; nt++) {
        const int col = bn + wn + nt * 8 + t2;
        if (mint) {
            mb[2 * nt]     = ((const int*)mask)[zb * Sq + col] != 0;
            mb[2 * nt + 1] = ((const int*)mask)[zb * Sq + col + 1] != 0;
        } else {
            mb[2 * nt]     = ((const unsigned char*)mask)[zb * Sq + col] != 0;
            mb[2 * nt + 1] = ((const unsigned char*)mask)[zb * Sq + col + 1] != 0;
        }
    }
    float stm[8], sts[8];
#pragma unroll
    for (int mt = 0; mt < 4; mt++)
#pragma unroll
        for (int h2 = 0; h2 < 2; h2++) {
            const int row = bm + wm + mt * 16 + g + h2 * 8;
            float* rp = attn + ((size_t)z * Sq + row) * Sq;
            float v8[8], tm = -INFINITY;
#pragma unroll
            for (int nt = 0; nt < 4; nt++) {
                float v0 = mb[2 * nt]     ? acc[mt][nt][h2 * 2 + 0] * 0.125f : NEG_INF;
                float v1 = mb[2 * nt + 1] ? acc[mt][nt][h2 * 2 + 1] * 0.125f : NEG_INF;
                *(float2*)(rp + bn + wn + nt * 8 + t2) = make_float2(v0, v1);
                v8[2 * nt] = v0; v8[2 * nt + 1] = v1;
                tm = fmaxf(tm, fmaxf(v0, v1));
            }
            float ts = 0.f;
            if (tm > -INFINITY) {
#pragma unroll
                for (int i = 0; i < 8; i++)
                    ts += ex2((v8[i] - tm) * CLOG2E);
            }
            stm[mt * 2 + h2] = tm; sts[mt * 2 + h2] = ts;
        }
#pragma unroll
    for (int o = 1; o <= 2; o <<= 1)
#pragma unroll
        for (int s = 0; s < 8; s++) {
            float om = __shfl_xor_sync(~0u, stm[s], o);
            float os = __shfl_xor_sync(~0u, sts[s], o);
            merge_ms(stm[s], sts[s], om, os);
        }
    if ((lane & 3) == 0) {
#pragma unroll
        for (int mt = 0; mt < 4; mt++)
#pragma unroll
            for (int h2 = 0; h2 < 2; h2++) {
                const int rl = wm + mt * 16 + g + h2 * 8;
                smM[rl * 4 + (warp & 3)] = stm[mt * 2 + h2];
                smS[rl * 4 + (warp & 3)] = sts[mt * 2 + h2];
            }
    }
    __syncthreads();
    if (tid < 128) {
        float m = -INFINITY, s = 0.f;
#pragma unroll
        for (int j = 0; j < 4; j++)
            merge_ms(m, s, smM[tid * 4 + j], smS[tid * 4 + j]);
        g_part[((size_t)z * Sq + bm + tid) * 16 + blockIdx.x] = make_float2(m, s);
    }
}

// ---------------------------------------------------------------------------
// Merge per-tile stats -> croff[row] = m*log2e + log2(sum)
// ---------------------------------------------------------------------------
__global__ void stats_merge_kernel() {
    const int r = blockIdx.x * blockDim.x + threadIdx.x;
    const float2* p = g_part + (size_t)r * 16;
    float m = -INFINITY, s = 0.f;
#pragma unroll
    for (int j = 0; j < 16; j++) {
        float2 v = p[j];
        merge_ms(m, s, v.x, v.y);
    }
    g_croff[r] = fmaf(m, CLOG2E, lg2(s));
}

// ---------------------------------------------------------------------------
// Ctx — R2 mainloop (BK=32, static smem, grid 1x16x32) with inline normalize:
// reads raw scores, p = ex2(s*log2e - croff), writes normalized attn in place,
// splits p into smem, MMAs with V -> f32 ctx in [B,S,D].
// ---------------------------------------------------------------------------
__global__ void __launch_bounds__(256) ctx_kernel(float* __restrict__ attn)
{
    constexpr int SA = 40, SB = 72;
    __shared__ __nv_bfloat16 Ah[128 * SA], Al[128 * SA];
    __shared__ __nv_bfloat16 Bh[32 * SB],  Bl[32 * SB];
    __shared__ float crf[128];

    const int z = blockIdx.z, zb = z / Hn, zh = z % Hn;
    float* P = attn + (size_t)z * Sq * Sq;
    const float* V = g_v + (size_t)z * Sq * DHd;
    const int bm = blockIdx.y * 128;

    const int tid = threadIdx.x, lane = tid & 31, warp = tid >> 5;
    const int wm = (warp >> 2) * 64;
    const int wn = (warp & 3) * 16;

    if (tid < 128) crf[tid] = g_croff[(size_t)z * Sq + bm + tid];
    __syncthreads();

    float acc[4][2][4];
#pragma unroll
    for (int i = 0; i < 4; i++)
#pragma unroll
        for (int j = 0; j < 2; j++)
#pragma unroll
            for (int q = 0; q < 4; q++) acc[i][j][q] = 0.f;

    const uint32_t aH = smem_u32(Ah), aL = smem_u32(Al);
    const uint32_t bH = smem_u32(Bh), bL = smem_u32(Bl);

    for (int k0 = 0; k0 < Sq; k0 += 32) {
        // P fill: read raw, normalize, write back, split to smem
#pragma unroll
        for (int r = 0; r < 4; r++) {
            const int m  = (tid >> 3) + r * 32;
            const int kq = (tid & 7) * 4;
            float* rp = P + (size_t)(bm + m) * Sq + k0 + kq;
            const float cr = crf[m];
            float4 v = *(float4*)rp;
            v.x = ex2(fmaf(v.x, CLOG2E, -cr));
            v.y = ex2(fmaf(v.y, CLOG2E, -cr));
            v.z = ex2(fmaf(v.z, CLOG2E, -cr));
            v.w = ex2(fmaf(v.w, CLOG2E, -cr));
            *(float4*)rp = v;
            __nv_bfloat16 h0, h1, h2, h3, l0, l1, l2, l3;
            split1(v.x, h0, l0); split1(v.y, h1, l1);
            split1(v.z, h2, l2); split1(v.w, h3, l3);
            *(__nv_bfloat162*)&Ah[m * SA + kq]     = __nv_bfloat162{h0, h1};
            *(__nv_bfloat162*)&Ah[m * SA + kq + 2] = __nv_bfloat162{h2, h3};
            *(__nv_bfloat162*)&Al[m * SA + kq]     = __nv_bfloat162{l0, l1};
            *(__nv_bfloat162*)&Al[m * SA + kq + 2] = __nv_bfloat162{l2, l3};
        }
        // V fill (32 x 64)
#pragma unroll
        for (int r = 0; r < 2; r++) {
            const int kr = (tid >> 4) + r * 16;
            const int n4 = (tid & 15) * 4;
            float4 v = *(const float4*)(V + (size_t)(k0 + kr) * DHd + n4);
            __nv_bfloat16 h0, h1, h2, h3, l0, l1, l2, l3;
            split1(v.x, h0, l0); split1(v.y, h1, l1);
            split1(v.z, h2, l2); split1(v.w, h3, l3);
            *(__nv_bfloat162*)&Bh[kr * SB + n4]     = __nv_bfloat162{h0, h1};
            *(__nv_bfloat162*)&Bh[kr * SB + n4 + 2] = __nv_bfloat162{h2, h3};
            *(__nv_bfloat162*)&Bl[kr * SB + n4]     = __nv_bfloat162{l0, l1};
            *(__nv_bfloat162*)&Bl[kr * SB + n4 + 2] = __nv_bfloat162{l2, l3};
        }
        __syncthreads();

#pragma unroll
        for (int kk = 0; kk < 32; kk += 16) {
            uint32_t ah[4][4], al[4][4];
            const int arow = wm + (lane & 7) + ((lane >> 3) & 1) * 8;
            const int acol = kk + (lane >> 4) * 8;
#pragma unroll
            for (int mt = 0; mt < 4; mt++) {
                const uint32_t off = (uint32_t)(((arow + mt * 16) * SA + acol) * 2);
                ldm4(ah[mt], aH + off);
                ldm4(al[mt], aL + off);
            }
            uint32_t bh[2][2], bl[2][2];
            {
                const int brow = kk + (lane & 7) + ((lane >> 3) & 1) * 8;
                const int bcol = wn + (lane >> 4) * 8;
                const uint32_t off = (uint32_t)((brow * SB + bcol) * 2);
                uint32_t t[4];
                ldm4t(t, bH + off);
                bh[0][0] = t[0]; bh[0][1] = t[1];
                bh[1][0] = t[2]; bh[1][1] = t[3];
                ldm4t(t, bL + off);
                bl[0][0] = t[0]; bl[0][1] = t[1];
                bl[1][0] = t[2]; bl[1][1] = t[3];
            }
#pragma unroll
            for (int mt = 0; mt < 4; mt++)
#pragma unroll
                for (int nt = 0; nt < 2; nt++) {
                    mma_bf16(acc[mt][nt], ah[mt], bh[nt]);
                    mma_bf16(acc[mt][nt], ah[mt], bl[nt]);
                    mma_bf16(acc[mt][nt], al[mt], bh[nt]);
                }
        }
        __syncthreads();
    }

    const int g = lane >> 2, t2 = (lane & 3) * 2;
#pragma unroll
    for (int mt = 0; mt < 4; mt++)
#pragma unroll
        for (int nt = 0; nt < 2; nt++) {
            const int col = wn + nt * 8 + t2;
#pragma unroll
            for (int h2 = 0; h2 < 2; h2++) {
                const int row = bm + wm + mt * 16 + g + h2 * 8;
                *(float2*)(g_ctx + ((size_t)zb * Sq + row) * Dm + zh * DHd + col)
                    = make_float2(acc[mt][nt][h2 * 2 + 0], acc[mt][nt][h2 * 2 + 1]);
            }
        }
}

// ---------------------------------------------------------------------------
// Launch. Inputs: qs ks vs mask Wq bq Wk bk Wv bv Wo bo.
// d_out: out [B,S,D] then attn [B,H,S,S].
// ---------------------------------------------------------------------------
extern "C" void kernel_launch(void* const* d_in, const int* in_sizes, int n_in,
                              void* d_out, int out_size)
{
    const float* qs = (const float*)d_in[0];
    const float* ks = (const float*)d_in[1];
    const float* vs = (const float*)d_in[2];
    const void*  mask = d_in[3];
    const float* Wq = (const float*)d_in[4];
    const float* bq = (const float*)d_in[5];
    const float* Wk = (const float*)d_in[6];
    const float* bk = (const float*)d_in[7];
    const float* Wv = (const float*)d_in[8];
    const float* bv = (const float*)d_in[9];
    const float* Wo = (const float*)d_in[10];
    const float* bo = (const float*)d_in[11];

    float* out  = (float*)d_out;
    float* attn = out + (size_t)Bz * Sq * Dm;

    float *gq, *gk, *gv, *gctx;
    cudaGetSymbolAddress((void**)&gq, g_q);
    cudaGetSymbolAddress((void**)&gk, g_k);
    cudaGetSymbolAddress((void**)&gv, g_v);
    cudaGetSymbolAddress((void**)&gctx, g_ctx);

    detect_mask_kernel<<<1, 256>>>((const unsigned char*)mask);

    dim3 gProj(Dm / 128, (Bz * Sq) / 128);  // (8, 32)
    proj_gemm<0><<<gProj, 256>>>(qs, Wq, bq, gq);
    proj_gemm<0><<<gProj, 256>>>(ks, Wk, bk, gk);
    proj_gemm<0><<<gProj, 256>>>(vs, Wv, bv, gv);

    scores_kernel<<<dim3(Sq / 128, Sq / 128, BH), 256>>>(mask, attn);

    stats_merge_kernel<<<(BH * Sq) / 256, 256>>>();

    ctx_kernel<<<dim3(1, Sq / 128, BH), 256>>>(attn);

    proj_gemm<1><<<gProj, 256>>>(gctx, Wo, bo, out);
}

// round 8
// speedup vs baseline: 1.4206x; 1.0919x over previous
#include <cuda_runtime.h>
#include <cuda_bf16.h>
#include <stdint.h>
#include <math.h>

// Problem constants
#define Bz  2
#define Sq  2048
#define Dm  1024
#define Hn  16
#define DHd 64
#define BH  (Bz * Hn)

// ---------------------------------------------------------------------------
// Scratch (allocation-free __device__ globals)
// ---------------------------------------------------------------------------
__device__ __align__(256) float g_q[(size_t)BH * Sq * DHd];
__device__ __align__(256) float g_k[(size_t)BH * Sq * DHd];
__device__ __align__(256) float g_v[(size_t)BH * Sq * DHd];
__device__ __align__(256) float g_ctx[(size_t)Bz * Sq * Dm];
__device__ int g_mask_is_int;

// ---------------------------------------------------------------------------
// Helpers
// ---------------------------------------------------------------------------
__device__ __forceinline__ uint32_t smem_u32(const void* p) {
    return (uint32_t)__cvta_generic_to_shared(p);
}
__device__ __forceinline__ void ldm4(uint32_t* r, uint32_t a) {
    asm volatile("ldmatrix.sync.aligned.m8n8.x4.shared.b16 {%0,%1,%2,%3},[%4];"
                 : "=r"(r[0]), "=r"(r[1]), "=r"(r[2]), "=r"(r[3]) : "r"(a));
}
__device__ __forceinline__ void ldm4t(uint32_t* r, uint32_t a) {
    asm volatile("ldmatrix.sync.aligned.m8n8.x4.trans.shared.b16 {%0,%1,%2,%3},[%4];"
                 : "=r"(r[0]), "=r"(r[1]), "=r"(r[2]), "=r"(r[3]) : "r"(a));
}
__device__ __forceinline__ void mma_bf16(float* c, const uint32_t* a, const uint32_t* b) {
    asm volatile(
        "mma.sync.aligned.m16n8k16.row.col.f32.bf16.bf16.f32 "
        "{%0,%1,%2,%3},{%4,%5,%6,%7},{%8,%9},{%0,%1,%2,%3};"
        : "+f"(c[0]), "+f"(c[1]), "+f"(c[2]), "+f"(c[3])
        : "r"(a[0]), "r"(a[1]), "r"(a[2]), "r"(a[3]), "r"(b[0]), "r"(b[1]));
}
__device__ __forceinline__ void split1(float x, __nv_bfloat16& h, __nv_bfloat16& l) {
    h = __float2bfloat16(x);
    l = __float2bfloat16(x - __bfloat162float(h));
}
__device__ __forceinline__ void split_to(float4 v, __nv_bfloat16* dh, __nv_bfloat16* dl) {
    __nv_bfloat16 h0, h1, h2, h3, l0, l1, l2, l3;
    split1(v.x, h0, l0); split1(v.y, h1, l1);
    split1(v.z, h2, l2); split1(v.w, h3, l3);
    *(__nv_bfloat162*)(dh)     = __nv_bfloat162{h0, h1};
    *(__nv_bfloat162*)(dh + 2) = __nv_bfloat162{h2, h3};
    *(__nv_bfloat162*)(dl)     = __nv_bfloat162{l0, l1};
    *(__nv_bfloat162*)(dl + 2) = __nv_bfloat162{l2, l3};
}
#define CP16(dst, src) \
    asm volatile("cp.async.cg.shared.global [%0], [%1], 16;" \
                 :: "r"(dst), "l"(src) : "memory")
#define CP_COMMIT() asm volatile("cp.async.commit_group;" ::: "memory")
#define CP_WAIT1()  asm volatile("cp.async.wait_group 1;" ::: "memory")
#define CP_WAIT0()  asm volatile("cp.async.wait_group 0;" ::: "memory")

// ---------------------------------------------------------------------------
// Mask dtype detector
// ---------------------------------------------------------------------------
__global__ void detect_mask_kernel(const unsigned char* __restrict__ m) {
    __shared__ int any;
    if (threadIdx.x == 0) any = 0;
    __syncthreads();
    int local = 0;
    for (int i = threadIdx.x; i < Bz * Sq; i += blockDim.x)
        if ((i & 3) && m[i]) local = 1;
    if (local) atomicOr(&any, 1);
    __syncthreads();
    if (threadIdx.x == 0) g_mask_is_int = (any == 0) ? 1 : 0;
}

// ---------------------------------------------------------------------------
// Projection GEMM — R2 math with cp.async double-buffered staging.
// 128x128x32 tiles, 8 warps, gridDim.z selects (A, W, bias, C).
// MODE 0: head-split epilogue; MODE 1: plain epilogue.
// Dynamic smem: Ar[2][128*36]f @0, Br[2][32*128]f @36864,
//               Ah @69632, Al @79872, Bh @90112, Bl @98816 (total 107520 B)
// ---------------------------------------------------------------------------
struct ProjArgs {
    const float* A[3]; const float* W[3]; const float* bias[3]; float* C[3];
};
#define SM_PROJ 107520

template <int MODE>
__global__ void __launch_bounds__(256) proj_gemm(ProjArgs args)
{
    constexpr int SA = 40, SB = 136;
    extern __shared__ char smc[];
    float* Ar = (float*)smc;
    float* Br = (float*)(smc + 36864);
    __nv_bfloat16* Ah = (__nv_bfloat16*)(smc + 69632);
    __nv_bfloat16* Al = (__nv_bfloat16*)(smc + 79872);
    __nv_bfloat16* Bh = (__nv_bfloat16*)(smc + 90112);
    __nv_bfloat16* Bl = (__nv_bfloat16*)(smc + 98816);

    const int z = blockIdx.z;
    const float* A = args.A[z];
    const float* W = args.W[z];
    const float* bias = args.bias[z];
    float* C = args.C[z];

    const int tid = threadIdx.x, lane = tid & 31, warp = tid >> 5;
    const int wm = (warp >> 2) * 64;
    const int wn = (warp & 3) * 32;
    const int bm = blockIdx.y * 128;
    const int bn = blockIdx.x * 128;

    float acc[4][4][4];
#pragma unroll
    for (int i = 0; i < 4; i++)
#pragma unroll
        for (int j = 0; j < 4; j++)
#pragma unroll
            for (int q = 0; q < 4; q++) acc[i][j][q] = 0.f;

    const uint32_t aH = smem_u32(Ah), aL = smem_u32(Al);
    const uint32_t bH = smem_u32(Bh), bL = smem_u32(Bl);

    // issue cp.async loads of K-tile k0 into stage s
    auto issue = [&](int s, int k0) {
        float* ArS = Ar + s * (128 * 36);
        float* BrS = Br + s * (32 * 128);
#pragma unroll
        for (int r = 0; r < 4; r++) {
            const int idx = tid + r * 256;
            const int row = idx >> 3, ch = (idx & 7) * 4;
            CP16(smem_u32(ArS + row * 36 + ch),
                 A + (size_t)(bm + row) * Dm + k0 + ch);
        }
#pragma unroll
        for (int r = 0; r < 4; r++) {
            const int idx = tid + r * 256;
            const int row = idx >> 5, ch = (idx & 31) * 4;
            CP16(smem_u32(BrS + row * 128 + ch),
                 W + (size_t)(k0 + row) * Dm + bn + ch);
        }
        CP_COMMIT();
    };

    issue(0, 0);
    for (int it = 0; it < Dm / 32; ++it) {
        const int s = it & 1;
        if (it + 1 < Dm / 32) { issue(s ^ 1, (it + 1) * 32); CP_WAIT1(); }
        else                  { CP_WAIT0(); }
        __syncthreads();   // staging ready AND previous MMA done

        // convert stage -> split bf16 smem (R2 fill indexing)
        float* ArS = Ar + s * (128 * 36);
        float* BrS = Br + s * (32 * 128);
#pragma unroll
        for (int r = 0; r < 4; r++) {
            const int m  = (tid >> 3) + r * 32;
            const int kq = (tid & 7) * 4;
            float4 v = *(const float4*)(ArS + m * 36 + kq);
            split_to(v, &Ah[m * SA + kq], &Al[m * SA + kq]);
        }
#pragma unroll
        for (int r = 0; r < 4; r++) {
            const int kr = (tid >> 5) + r * 8;
            const int n4 = (tid & 31) * 4;
            float4 v = *(const float4*)(BrS + kr * 128 + n4);
            split_to(v, &Bh[kr * SB + n4], &Bl[kr * SB + n4]);
        }
        __syncthreads();

#pragma unroll
        for (int kk = 0; kk < 32; kk += 16) {
            uint32_t ah[4][4], al[4][4];
            const int arow = wm + (lane & 7) + ((lane >> 3) & 1) * 8;
            const int acol = kk + (lane >> 4) * 8;
#pragma unroll
            for (int mt = 0; mt < 4; mt++) {
                const uint32_t off = (uint32_t)(((arow + mt * 16) * SA + acol) * 2);
                ldm4(ah[mt], aH + off);
                ldm4(al[mt], aL + off);
            }
            uint32_t bh[4][2], bl[4][2];
            const int brow = kk + (lane & 7) + ((lane >> 3) & 1) * 8;
#pragma unroll
            for (int sp = 0; sp < 2; sp++) {
                const int bcol = wn + sp * 16 + (lane >> 4) * 8;
                const uint32_t off = (uint32_t)((brow * SB + bcol) * 2);
                uint32_t t[4];
                ldm4t(t, bH + off);
                bh[2 * sp][0] = t[0]; bh[2 * sp][1] = t[1];
                bh[2 * sp + 1][0] = t[2]; bh[2 * sp + 1][1] = t[3];
                ldm4t(t, bL + off);
                bl[2 * sp][0] = t[0]; bl[2 * sp][1] = t[1];
                bl[2 * sp + 1][0] = t[2]; bl[2 * sp + 1][1] = t[3];
            }
#pragma unroll
            for (int mt = 0; mt < 4; mt++)
#pragma unroll
                for (int nt = 0; nt < 4; nt++) {
                    mma_bf16(acc[mt][nt], ah[mt], bh[nt]);
                    mma_bf16(acc[mt][nt], ah[mt], bl[nt]);
                    mma_bf16(acc[mt][nt], al[mt], bh[nt]);
                }
        }
    }

    const int g = lane >> 2, t2 = (lane & 3) * 2;
#pragma unroll
    for (int mt = 0; mt < 4; mt++)
#pragma unroll
        for (int nt = 0; nt < 4; nt++) {
            const int col = bn + wn + nt * 8 + t2;
#pragma unroll
            for (int h2 = 0; h2 < 2; h2++) {
                const int row = bm + wm + mt * 16 + g + h2 * 8;
                float c0 = acc[mt][nt][h2 * 2 + 0] + bias[col];
                float c1 = acc[mt][nt][h2 * 2 + 1] + bias[col + 1];
                if (MODE == 0) {
                    const int bb = row >> 11, ss = row & (Sq - 1);
                    const int hh = col >> 6,  dh = col & (DHd - 1);
                    *(float2*)(C + (((size_t)(bb * Hn + hh)) * Sq + ss) * DHd + dh)
                        = make_float2(c0, c1);
                } else {
                    *(float2*)(C + (size_t)row * Dm + col) = make_float2(c0, c1);
                }
            }
        }
}

// ---------------------------------------------------------------------------
// Scores — EXACT R2 body (static smem, 2 K-iters, no pipelining needed).
// ---------------------------------------------------------------------------
__global__ void __launch_bounds__(256) scores_kernel(
    const void* __restrict__ mask, float* __restrict__ attn)
{
    constexpr int SA = 40, SB = 40;
    __shared__ __nv_bfloat16 Ah[128 * SA], Al[128 * SA];
    __shared__ __nv_bfloat16 Bh[128 * SB], Bl[128 * SB];

    const int z = blockIdx.z, zb = z / Hn;
    const float* q = g_q + (size_t)z * Sq * DHd;
    const float* k = g_k + (size_t)z * Sq * DHd;

    const int tid = threadIdx.x, lane = tid & 31, warp = tid >> 5;
    const int wm = (warp >> 2) * 64;
    const int wn = (warp & 3) * 32;
    const int bm = blockIdx.y * 128;
    const int bn = blockIdx.x * 128;

    float acc[4][4][4];
#pragma unroll
    for (int i = 0; i < 4; i++)
#pragma unroll
        for (int j = 0; j < 4; j++)
#pragma unroll
            for (int q2 = 0; q2 < 4; q2++) acc[i][j][q2] = 0.f;

    const uint32_t aH = smem_u32(Ah), aL = smem_u32(Al);
    const uint32_t bH = smem_u32(Bh), bL = smem_u32(Bl);

    for (int k0 = 0; k0 < DHd; k0 += 32) {
#pragma unroll
        for (int r = 0; r < 4; r++) {
            const int m  = (tid >> 3) + r * 32;
            const int kq = (tid & 7) * 4;
            float4 a = *(const float4*)(q + (size_t)(bm + m) * DHd + k0 + kq);
            split_to(a, &Ah[m * SA + kq], &Al[m * SA + kq]);
            float4 b = *(const float4*)(k + (size_t)(bn + m) * DHd + k0 + kq);
            split_to(b, &Bh[m * SB + kq], &Bl[m * SB + kq]);
        }
        __syncthreads();

#pragma unroll
        for (int kk = 0; kk < 32; kk += 16) {
            uint32_t ah[4][4], al[4][4];
            const int arow = wm + (lane & 7) + ((lane >> 3) & 1) * 8;
            const int acol = kk + (lane >> 4) * 8;
#pragma unroll
            for (int mt = 0; mt < 4; mt++) {
                const uint32_t off = (uint32_t)(((arow + mt * 16) * SA + acol) * 2);
                ldm4(ah[mt], aH + off);
                ldm4(al[mt], aL + off);
            }
            uint32_t bh[4][2], bl[4][2];
#pragma unroll
            for (int sp = 0; sp < 2; sp++) {
                const int brow = wn + sp * 16 + (lane & 7) + ((lane >> 3) & 1) * 8;
                const int bcol = kk + (lane >> 4) * 8;
                const uint32_t off = (uint32_t)((brow * SB + bcol) * 2);
                uint32_t t[4];
                ldm4(t, bH + off);
                bh[2 * sp][0] = t[0]; bh[2 * sp + 1][0] = t[1];
                bh[2 * sp][1] = t[2]; bh[2 * sp + 1][1] = t[3];
                ldm4(t, bL + off);
                bl[2 * sp][0] = t[0]; bl[2 * sp + 1][0] = t[1];
                bl[2 * sp][1] = t[2]; bl[2 * sp + 1][1] = t[3];
            }
#pragma unroll
            for (int mt = 0; mt < 4; mt++)
#pragma unroll
                for (int nt = 0; nt < 4; nt++) {
                    mma_bf16(acc[mt][nt], ah[mt], bh[nt]);
                    mma_bf16(acc[mt][nt], ah[mt], bl[nt]);
                    mma_bf16(acc[mt][nt], al[mt], bh[nt]);
                }
        }
        __syncthreads();
    }

    const int g = lane >> 2, t2 = (lane & 3) * 2;
    const int mint = g_mask_is_int;
    const float NEG_INF = __int_as_float(0xff800000);
#pragma unroll
    for (int nt = 0; nt < 4; nt++) {
        const int col = bn + wn + nt * 8 + t2;
        bool m0, m1;
        if (mint) {
            m0 = ((const int*)mask)[zb * Sq + col] != 0;
            m1 = ((const int*)mask)[zb * Sq + col + 1] != 0;
        } else {
            m0 = ((const unsigned char*)mask)[zb * Sq + col] != 0;
            m1 = ((const unsigned char*)mask)[zb * Sq + col + 1] != 0;
        }
#pragma unroll
        for (int mt = 0; mt < 4; mt++)
#pragma unroll
            for (int h2 = 0; h2 < 2; h2++) {
                const int row = bm + wm + mt * 16 + g + h2 * 8;
                float v0 = m0 ? acc[mt][nt][h2 * 2 + 0] * 0.125f : NEG_INF;
                float v1 = m1 ? acc[mt][nt][h2 * 2 + 1] * 0.125f : NEG_INF;
                *(float2*)(attn + ((size_t)z * Sq + row) * Sq + col) = make_float2(v0, v1);
            }
    }
}

// ---------------------------------------------------------------------------
// In-place row softmax over S=2048 (R2 exact)
// ---------------------------------------------------------------------------
__global__ void __launch_bounds__(256) softmax_kernel(float* __restrict__ attn)
{
    const size_t row = blockIdx.x;
    float4* p = (float4*)(attn + row * Sq);
    const int tid = threadIdx.x;

    float4 v0 = p[tid];
    float4 v1 = p[tid + 256];

    float m = fmaxf(fmaxf(fmaxf(v0.x, v0.y), fmaxf(v0.z, v0.w)),
                    fmaxf(fmaxf(v1.x, v1.y), fmaxf(v1.z, v1.w)));
#pragma unroll
    for (int o = 16; o; o >>= 1) m = fmaxf(m, __shfl_xor_sync(~0u, m, o));

    __shared__ float sred[8];
    if ((tid & 31) == 0) sred[tid >> 5] = m;
    __syncthreads();
    if (tid < 32) {
        float t = (tid < 8) ? sred[tid] : __int_as_float(0xff800000);
#pragma unroll
        for (int o = 4; o; o >>= 1) t = fmaxf(t, __shfl_xor_sync(~0u, t, o));
        if (tid == 0) sred[0] = t;
    }
    __syncthreads();
    m = sred[0];
    __syncthreads();

    float e[8];
    e[0] = expf(v0.x - m); e[1] = expf(v0.y - m);
    e[2] = expf(v0.z - m); e[3] = expf(v0.w - m);
    e[4] = expf(v1.x - m); e[5] = expf(v1.y - m);
    e[6] = expf(v1.z - m); e[7] = expf(v1.w - m);
    float s = e[0] + e[1] + e[2] + e[3] + e[4] + e[5] + e[6] + e[7];
#pragma unroll
    for (int o = 16; o; o >>= 1) s += __shfl_xor_sync(~0u, s, o);
    if ((tid & 31) == 0) sred[tid >> 5] = s;
    __syncthreads();
    if (tid < 32) {
        float t = (tid < 8) ? sred[tid] : 0.f;
#pragma unroll
        for (int o = 4; o; o >>= 1) t += __shfl_xor_sync(~0u, t, o);
        if (tid == 0) sred[0] = t;
    }
    __syncthreads();
    const float inv = 1.f / sred[0];

    v0 = make_float4(e[0] * inv, e[1] * inv, e[2] * inv, e[3] * inv);
    v1 = make_float4(e[4] * inv, e[5] * inv, e[6] * inv, e[7] * inv);
    p[tid]       = v0;
    p[tid + 256] = v1;
}

// ---------------------------------------------------------------------------
// Ctx — R2 math with cp.async double-buffered staging (64 K-iters).
// Dynamic smem: Pr[2][128*36]f @0, Vr[2][32*64]f @36864,
//               Ah @53248, Al @63488, Bh @73728, Bl @78336 (total 82944 B)
// ---------------------------------------------------------------------------
#define SM_CTX 82944
__global__ void __launch_bounds__(256) ctx_kernel(const float* __restrict__ attn)
{
    constexpr int SA = 40, SB = 72;
    extern __shared__ char smc[];
    float* Pr = (float*)smc;
    float* Vr = (float*)(smc + 36864);
    __nv_bfloat16* Ah = (__nv_bfloat16*)(smc + 53248);
    __nv_bfloat16* Al = (__nv_bfloat16*)(smc + 63488);
    __nv_bfloat16* Bh = (__nv_bfloat16*)(smc + 73728);
    __nv_bfloat16* Bl = (__nv_bfloat16*)(smc + 78336);

    const int z = blockIdx.z, zb = z / Hn, zh = z % Hn;
    const float* P = attn + (size_t)z * Sq * Sq;
    const float* V = g_v + (size_t)z * Sq * DHd;
    const int bm = blockIdx.y * 128;

    const int tid = threadIdx.x, lane = tid & 31, warp = tid >> 5;
    const int wm = (warp >> 2) * 64;
    const int wn = (warp & 3) * 16;

    float acc[4][2][4];
#pragma unroll
    for (int i = 0; i < 4; i++)
#pragma unroll
        for (int j = 0; j < 2; j++)
#pragma unroll
            for (int q = 0; q < 4; q++) acc[i][j][q] = 0.f;

    const uint32_t aH = smem_u32(Ah), aL = smem_u32(Al);
    const uint32_t bH = smem_u32(Bh), bL = smem_u32(Bl);

    auto issue = [&](int s, int k0) {
        float* PrS = Pr + s * (128 * 36);
        float* VrS = Vr + s * (32 * 64);
#pragma unroll
        for (int r = 0; r < 4; r++) {
            const int idx = tid + r * 256;
            const int row = idx >> 3, ch = (idx & 7) * 4;
            CP16(smem_u32(PrS + row * 36 + ch),
                 P + (size_t)(bm + row) * Sq + k0 + ch);
        }
#pragma unroll
        for (int r = 0; r < 2; r++) {
            const int idx = tid + r * 256;
            const int row = idx >> 4, ch = (idx & 15) * 4;
            CP16(smem_u32(VrS + row * 64 + ch),
                 V + (size_t)(k0 + row) * DHd + ch);
        }
        CP_COMMIT();
    };

    issue(0, 0);
    for (int it = 0; it < Sq / 32; ++it) {
        const int s = it & 1;
        if (it + 1 < Sq / 32) { issue(s ^ 1, (it + 1) * 32); CP_WAIT1(); }
        else                  { CP_WAIT0(); }
        __syncthreads();

        float* PrS = Pr + s * (128 * 36);
        float* VrS = Vr + s * (32 * 64);
#pragma unroll
        for (int r = 0; r < 4; r++) {
            const int m  = (tid >> 3) + r * 32;
            const int kq = (tid & 7) * 4;
            float4 v = *(const float4*)(PrS + m * 36 + kq);
            split_to(v, &Ah[m * SA + kq], &Al[m * SA + kq]);
        }
#pragma unroll
        for (int r = 0; r < 2; r++) {
            const int kr = (tid >> 4) + r * 16;
            const int n4 = (tid & 15) * 4;
            float4 v = *(const float4*)(VrS + kr * 64 + n4);
            split_to(v, &Bh[kr * SB + n4], &Bl[kr * SB + n4]);
        }
        __syncthreads();

#pragma unroll
        for (int kk = 0; kk < 32; kk += 16) {
            uint32_t ah[4][4], al[4][4];
            const int arow = wm + (lane & 7) + ((lane >> 3) & 1) * 8;
            const int acol = kk + (lane >> 4) * 8;
#pragma unroll
            for (int mt = 0; mt < 4; mt++) {
                const uint32_t off = (uint32_t)(((arow + mt * 16) * SA + acol) * 2);
                ldm4(ah[mt], aH + off);
                ldm4(al[mt], aL + off);
            }
            uint32_t bh[2][2], bl[2][2];
            {
                const int brow = kk + (lane & 7) + ((lane >> 3) & 1) * 8;
                const int bcol = wn + (lane >> 4) * 8;
                const uint32_t off = (uint32_t)((brow * SB + bcol) * 2);
                uint32_t t[4];
                ldm4t(t, bH + off);
                bh[0][0] = t[0]; bh[0][1] = t[1];
                bh[1][0] = t[2]; bh[1][1] = t[3];
                ldm4t(t, bL + off);
                bl[0][0] = t[0]; bl[0][1] = t[1];
                bl[1][0] = t[2]; bl[1][1] = t[3];
            }
#pragma unroll
            for (int mt = 0; mt < 4; mt++)
#pragma unroll
                for (int nt = 0; nt < 2; nt++) {
                    mma_bf16(acc[mt][nt], ah[mt], bh[nt]);
                    mma_bf16(acc[mt][nt], ah[mt], bl[nt]);
                    mma_bf16(acc[mt][nt], al[mt], bh[nt]);
                }
        }
    }

    const int g = lane >> 2, t2 = (lane & 3) * 2;
#pragma unroll
    for (int mt = 0; mt < 4; mt++)
#pragma unroll
        for (int nt = 0; nt < 2; nt++) {
            const int col = wn + nt * 8 + t2;
#pragma unroll
            for (int h2 = 0; h2 < 2; h2++) {
                const int row = bm + wm + mt * 16 + g + h2 * 8;
                *(float2*)(g_ctx + ((size_t)zb * Sq + row) * Dm + zh * DHd + col)
                    = make_float2(acc[mt][nt][h2 * 2 + 0], acc[mt][nt][h2 * 2 + 1]);
            }
        }
}

// ---------------------------------------------------------------------------
// Launch. Inputs: qs ks vs mask Wq bq Wk bk Wv bv Wo bo.
// d_out: out [B,S,D] then attn [B,H,S,S].
// ---------------------------------------------------------------------------
extern "C" void kernel_launch(void* const* d_in, const int* in_sizes, int n_in,
                              void* d_out, int out_size)
{
    const float* qs = (const float*)d_in[0];
    const float* ks = (const float*)d_in[1];
    const float* vs = (const float*)d_in[2];
    const void*  mask = d_in[3];
    const float* Wq = (const float*)d_in[4];
    const float* bq = (const float*)d_in[5];
    const float* Wk = (const float*)d_in[6];
    const float* bk = (const float*)d_in[7];
    const float* Wv = (const float*)d_in[8];
    const float* bv = (const float*)d_in[9];
    const float* Wo = (const float*)d_in[10];
    const float* bo = (const float*)d_in[11];

    float* out  = (float*)d_out;
    float* attn = out + (size_t)Bz * Sq * Dm;

    cudaFuncSetAttribute(proj_gemm<0>, cudaFuncAttributeMaxDynamicSharedMemorySize, SM_PROJ);
    cudaFuncSetAttribute(proj_gemm<1>, cudaFuncAttributeMaxDynamicSharedMemorySize, SM_PROJ);
    cudaFuncSetAttribute(ctx_kernel,  cudaFuncAttributeMaxDynamicSharedMemorySize, SM_CTX);

    float *gq, *gk, *gv, *gctx;
    cudaGetSymbolAddress((void**)&gq, g_q);
    cudaGetSymbolAddress((void**)&gk, g_k);
    cudaGetSymbolAddress((void**)&gv, g_v);
    cudaGetSymbolAddress((void**)&gctx, g_ctx);

    detect_mask_kernel<<<1, 256>>>((const unsigned char*)mask);

    // merged Q/K/V projection: gridDim.z = 3
    ProjArgs pa;
    pa.A[0] = qs; pa.A[1] = ks; pa.A[2] = vs;
    pa.W[0] = Wq; pa.W[1] = Wk; pa.W[2] = Wv;
    pa.bias[0] = bq; pa.bias[1] = bk; pa.bias[2] = bv;
    pa.C[0] = gq; pa.C[1] = gk; pa.C[2] = gv;
    proj_gemm<0><<<dim3(Dm / 128, (Bz * Sq) / 128, 3), 256, SM_PROJ>>>(pa);

    scores_kernel<<<dim3(Sq / 128, Sq / 128, BH), 256>>>(mask, attn);

    softmax_kernel<<<(unsigned)((size_t)BH * Sq), 256>>>(attn);

    ctx_kernel<<<dim3(1, Sq / 128, BH), 256, SM_CTX>>>(attn);

    ProjArgs po;
    po.A[0] = gctx; po.W[0] = Wo; po.bias[0] = bo; po.C[0] = out;
    po.A[1] = po.A[2] = nullptr; po.W[1] = po.W[2] = nullptr;
    po.bias[1] = po.bias[2] = nullptr; po.C[1] = po.C[2] = nullptr;
    proj_gemm<1><<<dim3(Dm / 128, (Bz * Sq) / 128, 1), 256, SM_PROJ>>>(po);
}